// round 15
// baseline (speedup 1.0000x reference)
#include <cuda_runtime.h>
#include <cuda_bf16.h>
#include <math.h>
#include <stdint.h>

#define MAXN 50000
#define MAXE 800000
#define D 128
#define NLAYERS 9
#define NGRAPHS 256
#define ONE_PLUS_EPS 1.00001f
#define NPREP_T (NLAYERS * 8 * 16 * 32)   // 36864 prepack threads
#define DBINS 128

// ---------------- scratch (static device globals; zero-initialized at load) ----------------
__device__ float    g_h[MAXN * D];
__device__ float    g_h2[MAXN * D];
__device__ uint32_t g_Ahi[MAXN * 64];     // A split: bf16x2 hi pairs {dim 2j, 2j+1}
__device__ uint32_t g_Alo[MAXN * 64];     // A split: bf16x2 lo pairs
__device__ int      g_rowoff[MAXN + 1];
__device__ int      g_cursor[MAXN];       // STATICALLY ZERO; restored to zero at end of launch
__device__ int      g_srcoff[MAXE];       // src node BYTE offset (src*512) per CSR slot
__device__ float4   g_ea4[MAXE];
__device__ float    g_pooled[NGRAPHS * D];
__device__ int      g_perm[MAXN];         // nodes sorted by degree
__device__ int      g_dcur[DBINS];        // degree-bin cursors (recomputed every launch)
// W prepacked into mma b-fragment layout: [layer][kc(8)][nt(16)][lane(32)] = {bh0,bh1,bl0,bl1}
__device__ uint4    g_Wpk[NPREP_T];

// ---------------- helpers ----------------
__device__ __forceinline__ unsigned short f2bf(float x) {
    __nv_bfloat16 b = __float2bfloat16_rn(x);
    return *(unsigned short*)&b;
}
__device__ __forceinline__ float bf2f(unsigned short u) {
    __nv_bfloat16 b = *(__nv_bfloat16*)&u;
    return __bfloat162float(b);
}
__device__ __forceinline__ uint32_t pack_hi(float a, float b) {
    return (uint32_t)f2bf(a) | ((uint32_t)f2bf(b) << 16);
}
__device__ __forceinline__ uint32_t pack_lo(float a, float b) {
    unsigned short ha = f2bf(a), hb = f2bf(b);
    return (uint32_t)f2bf(a - bf2f(ha)) | ((uint32_t)f2bf(b - bf2f(hb)) << 16);
}
__device__ __forceinline__ void mma_bf16(float* c, uint32_t a0, uint32_t a1, uint32_t a2, uint32_t a3,
                                         uint32_t b0, uint32_t b1) {
    asm volatile(
        "mma.sync.aligned.m16n8k16.row.col.f32.bf16.bf16.f32 "
        "{%0,%1,%2,%3}, {%4,%5,%6,%7}, {%8,%9}, {%0,%1,%2,%3};"
        : "+f"(c[0]), "+f"(c[1]), "+f"(c[2]), "+f"(c[3])
        : "r"(a0), "r"(a1), "r"(a2), "r"(a3), "r"(b0), "r"(b1));
}

// ---------------- fused prologue: hist + W prepack + h init ----------------
__global__ __launch_bounds__(256) void fused_prep_kernel(const int* __restrict__ dst, int E,
                                                         const float* __restrict__ convw,
                                                         const float* __restrict__ x,
                                                         const float* __restrict__ Wv,
                                                         int N, int nhist, int nprep) {
    int b = blockIdx.x;
    int tid = threadIdx.x;
    if (b < nhist) {
        int e = b * 256 + tid;
        if (e < E) atomicAdd(&g_cursor[dst[e]], 1);
    } else if (b < nhist + nprep) {
        int idx = (b - nhist) * 256 + tid;
        if (idx < NPREP_T) {
            int lane = idx & 31;
            int nt = (idx >> 5) & 15;
            int kc = (idx >> 9) & 7;
            int l = idx >> 12;
            const float* W = convw + (long)l * D * D;
            int k0 = kc * 16 + (lane & 3) * 2;
            int n = nt * 8 + (lane >> 2);
            float w00 = W[(k0 + 0) * D + n];
            float w01 = W[(k0 + 1) * D + n];
            float w08 = W[(k0 + 8) * D + n];
            float w09 = W[(k0 + 9) * D + n];
            uint4 o;
            o.x = pack_hi(w00, w01);
            o.y = pack_hi(w08, w09);
            o.z = pack_lo(w00, w01);
            o.w = pack_lo(w08, w09);
            g_Wpk[idx] = o;
        }
    } else {
        __shared__ float xr[2][13];
        int sub = tid >> 7;
        int t = tid & 127;
        int node = (b - nhist - nprep) * 2 + sub;
        if (node < N) {
            if (t < 13) xr[sub][t] = x[(long)node * 13 + t];
        }
        __syncthreads();
        if (node < N) {
            float s = 0.f;
#pragma unroll
            for (int k = 0; k < 13; k++) s = fmaf(xr[sub][k], Wv[k * D + t], s);
            g_h[(long)node * D + t] = s;
        }
    }
}

// ---------------- single-block scan: degrees -> offsets; degree-bin offsets ----------------
__global__ void scan_kernel(int N) {
    __shared__ int sums[1024];
    __shared__ int dhist[DBINS];
    int t = threadIdx.x;
    if (t < DBINS) dhist[t] = 0;
    __syncthreads();
    int chunk = (N + 1023) >> 10;
    int b0 = t * chunk;
    int b1 = min(b0 + chunk, N);
    int s = 0;
    for (int i = b0; i < b1; i++) {
        int dv = g_cursor[i];
        s += dv;
        atomicAdd(&dhist[min(dv, DBINS - 1)], 1);
    }
    sums[t] = s;
    __syncthreads();
    for (int off = 1; off < 1024; off <<= 1) {
        int v = (t >= off) ? sums[t - off] : 0;
        __syncthreads();
        sums[t] += v;
        __syncthreads();
    }
    int base = (t == 0) ? 0 : sums[t - 1];
    for (int i = b0; i < b1; i++) {
        int dv = g_cursor[i];
        g_rowoff[i] = base;
        g_cursor[i] = base;
        base += dv;
    }
    if (t == 1023) g_rowoff[N] = sums[1023];
    if (t == 0) {
        int acc = 0;
#pragma unroll 8
        for (int i = 0; i < DBINS; i++) {
            int c = dhist[i];
            g_dcur[i] = acc;
            acc += c;
        }
    }
}

// ---------------- edge scatter + degree-sorted node permutation ----------------
__global__ void scatter_kernel(const int* __restrict__ src, const int* __restrict__ dst,
                               const float4* __restrict__ attr4, int E, int N, int nhist) {
    int b = blockIdx.x;
    int tid = threadIdx.x;
    if (b < nhist) {
        int e = b * 256 + tid;
        if (e >= E) return;
        int d = dst[e];
        int p = atomicAdd(&g_cursor[d], 1);
        g_srcoff[p] = src[e] << 9;
        g_ea4[p] = attr4[e];
    } else {
        int i = (b - nhist) * 256 + tid;
        if (i >= N) return;
        int deg = g_rowoff[i + 1] - g_rowoff[i];
        int pos = atomicAdd(&g_dcur[min(deg, DBINS - 1)], 1);
        g_perm[pos] = i;
    }
}

// ---------------- fused layer: aggregation + mma GEMM, per-node dependency ----------------
// Block owns 128 degree-similar nodes (perm[base..base+127]), 512 threads.
// Phase 1: warp-per-node aggregation (8 rounds/warp) -> bf16 hi/lo fragments in global.
// Phase 2: R10 mma GEMM over these nodes; hn[node] = relu(A @ W + bias) + hp[node].
__global__ __launch_bounds__(512) void layer_fused_kernel(int l,
                                                          const float* __restrict__ We,
                                                          const float* __restrict__ bias,
                                                          const float* __restrict__ hp,
                                                          float* __restrict__ hn, int N) {
    __shared__ int nodes[128];
    int tid = threadIdx.x;
    int wid = tid >> 5;
    int lane = tid & 31;
    int base = blockIdx.x * 128;

    if (tid < 128) nodes[tid] = (base + tid < N) ? g_perm[base + tid] : -1;
    __syncthreads();

    // ======== phase 1: aggregation ========
    {
        float wk[4][4];
#pragma unroll
        for (int k = 0; k < 4; k++) {
            float4 t = *(const float4*)&We[k * D + lane * 4];
            wk[k][0] = t.x; wk[k][1] = t.y; wk[k][2] = t.z; wk[k][3] = t.w;
        }
        const char* hpc = (const char*)hp + lane * 16;

#pragma unroll
        for (int j = 0; j < 8; j++) {
            int node = nodes[wid * 8 + j];
            if (node < 0) continue;
            float4 acc;
            {
                float4 hv = *(const float4*)(hpc + ((long)node << 9));
                acc.x = ONE_PLUS_EPS * hv.x;
                acc.y = ONE_PLUS_EPS * hv.y;
                acc.z = ONE_PLUS_EPS * hv.z;
                acc.w = ONE_PLUS_EPS * hv.w;
            }
            int e0 = g_rowoff[node];
            int e1 = g_rowoff[node + 1];
#pragma unroll 4
            for (int e = e0; e < e1; e++) {
                int o = g_srcoff[e];
                float4 a = g_ea4[e];
                float4 hs = *(const float4*)(hpc + o);
                float m0 = fmaf(a.x, wk[0][0], fmaf(a.y, wk[1][0], fmaf(a.z, wk[2][0], fmaf(a.w, wk[3][0], hs.x))));
                float m1 = fmaf(a.x, wk[0][1], fmaf(a.y, wk[1][1], fmaf(a.z, wk[2][1], fmaf(a.w, wk[3][1], hs.y))));
                float m2 = fmaf(a.x, wk[0][2], fmaf(a.y, wk[1][2], fmaf(a.z, wk[2][2], fmaf(a.w, wk[3][2], hs.z))));
                float m3 = fmaf(a.x, wk[0][3], fmaf(a.y, wk[1][3], fmaf(a.z, wk[2][3], fmaf(a.w, wk[3][3], hs.w))));
                acc.x += fmaxf(m0, 0.f);
                acc.y += fmaxf(m1, 0.f);
                acc.z += fmaxf(m2, 0.f);
                acc.w += fmaxf(m3, 0.f);
            }
            uint2 hi = make_uint2(pack_hi(acc.x, acc.y), pack_hi(acc.z, acc.w));
            uint2 lo = make_uint2(pack_lo(acc.x, acc.y), pack_lo(acc.z, acc.w));
            *(uint2*)&g_Ahi[(long)node * 64 + lane * 2] = hi;
            *(uint2*)&g_Alo[(long)node * 64 + lane * 2] = lo;
        }
    }
    __syncthreads();   // global writes above are visible block-wide after this

    // ======== phase 2: mma GEMM over the block's nodes ========
    {
        int g = lane >> 2;
        int tg = lane & 3;
        int rowgrp = wid & 7;
        int colhalf = wid >> 3;
        int n1 = nodes[rowgrp * 16 + g];
        int n2 = nodes[rowgrp * 16 + g + 8];
        bool v1 = n1 >= 0;
        bool v2 = n2 >= 0;
        long r1 = v1 ? (long)n1 : 0;
        long r2 = v2 ? (long)n2 : 0;

        const uint4* __restrict__ wbase = &g_Wpk[(long)l * 4096 + colhalf * 8 * 32 + lane];

        float acc[8][4];
#pragma unroll
        for (int nt = 0; nt < 8; nt++)
#pragma unroll
            for (int j = 0; j < 4; j++) acc[nt][j] = 0.f;

#pragma unroll
        for (int kc = 0; kc < 8; kc++) {
            long i1 = r1 * 64 + kc * 8 + tg;
            long i2 = r2 * 64 + kc * 8 + tg;
            uint32_t ah0 = v1 ? g_Ahi[i1]     : 0u;
            uint32_t ah2 = v1 ? g_Ahi[i1 + 4] : 0u;
            uint32_t ah1 = v2 ? g_Ahi[i2]     : 0u;
            uint32_t ah3 = v2 ? g_Ahi[i2 + 4] : 0u;
            uint32_t al0 = v1 ? g_Alo[i1]     : 0u;
            uint32_t al2 = v1 ? g_Alo[i1 + 4] : 0u;
            uint32_t al1 = v2 ? g_Alo[i2]     : 0u;
            uint32_t al3 = v2 ? g_Alo[i2 + 4] : 0u;

            const uint4* bp = wbase + (long)kc * 512;
#pragma unroll
            for (int nt = 0; nt < 8; nt++) {
                uint4 b = bp[nt * 32];
                mma_bf16(acc[nt], ah0, ah1, ah2, ah3, b.x, b.y);  // Ah @ Bh
                mma_bf16(acc[nt], ah0, ah1, ah2, ah3, b.z, b.w);  // Ah @ Bl
                mma_bf16(acc[nt], al0, al1, al2, al3, b.x, b.y);  // Al @ Bh
            }
        }

#pragma unroll
        for (int nt = 0; nt < 8; nt++) {
            int c0 = colhalf * 64 + nt * 8 + tg * 2;
            float2 bb = *(const float2*)&bias[c0];
            if (v1) {
                float2 h = *(const float2*)&hp[r1 * D + c0];
                float2 o;
                o.x = fmaxf(acc[nt][0] + bb.x, 0.f) + h.x;
                o.y = fmaxf(acc[nt][1] + bb.y, 0.f) + h.y;
                *(float2*)&hn[r1 * D + c0] = o;
            }
            if (v2) {
                float2 h = *(const float2*)&hp[r2 * D + c0];
                float2 o;
                o.x = fmaxf(acc[nt][2] + bb.x, 0.f) + h.x;
                o.y = fmaxf(acc[nt][3] + bb.y, 0.f) + h.y;
                *(float2*)&hn[r2 * D + c0] = o;
            }
        }
    }
}

// ---------------- mean pool per graph (batch sorted int32) ----------------
__global__ void pool_kernel(const int* __restrict__ batch, const float* __restrict__ h, int N) {
    int g = blockIdx.x;
    int d = threadIdx.x;
    int lo = 0, hi = N;
    while (lo < hi) { int m = (lo + hi) >> 1; if (batch[m] < g) lo = m + 1; else hi = m; }
    int start = lo;
    lo = start; hi = N;
    while (lo < hi) { int m = (lo + hi) >> 1; if (batch[m] < g + 1) lo = m + 1; else hi = m; }
    int end = lo;
    float s = 0.f;
    for (int n = start; n < end; n++) s += h[(long)n * D + d];
    float cnt = (float)(end - start);
    g_pooled[g * D + d] = s / fmaxf(cnt, 1.0f);
}

// ---------------- MLP head ----------------
__global__ __launch_bounds__(512) void mlp_kernel(const float* __restrict__ Wh1,
                                                  const float* __restrict__ bh1,
                                                  const float* __restrict__ Wh2,
                                                  const float* __restrict__ bh2,
                                                  float* __restrict__ out) {
    int g = blockIdx.x;
    int j = threadIdx.x;
    __shared__ float p[D];
    __shared__ float red[512];
    if (j < D) p[j] = g_pooled[g * D + j];
    __syncthreads();
    float s = bh1[j];
#pragma unroll 8
    for (int k = 0; k < D; k++) s = fmaf(p[k], Wh1[k * 512 + j], s);
    float ge = 0.5f * s * (1.0f + erff(s * 0.70710678118654752f));
    red[j] = ge * Wh2[j];
    __syncthreads();
    for (int off = 256; off > 0; off >>= 1) {
        if (j < off) red[j] += red[j + off];
        __syncthreads();
    }
    if (j == 0) out[g] = red[0] + bh2[0];
}

// ---------------- restore cursor invariant ----------------
__global__ void zero_cursor_kernel(int N) {
    int i = blockIdx.x * blockDim.x + threadIdx.x;
    if (i < N) g_cursor[i] = 0;
}

// ---------------- launcher ----------------
extern "C" void kernel_launch(void* const* d_in, const int* in_sizes, int n_in,
                              void* d_out, int out_size) {
    const float* x     = (const float*)d_in[0];
    const int*   ei    = (const int*)d_in[1];
    const float* eattr = (const float*)d_in[2];
    const int*   batch = (const int*)d_in[3];
    const float* Wv    = (const float*)d_in[4];
    const float* We    = (const float*)d_in[5];
    const float* convw = (const float*)d_in[6];
    const float* convb = (const float*)d_in[7];
    const float* Wh1   = (const float*)d_in[8];
    const float* bh1   = (const float*)d_in[9];
    const float* Wh2   = (const float*)d_in[10];
    const float* bh2   = (const float*)d_in[11];
    float* out = (float*)d_out;

    int N = in_sizes[0] / 13;
    int E = in_sizes[2] / 4;
    int G = out_size;

    const int* src = ei;
    const int* dst = ei + E;

    int nhist = (E + 255) / 256;
    int nprep = (NPREP_T + 255) / 256;
    int ninit = (N + 1) / 2;
    int nnode = (N + 255) / 256;

    fused_prep_kernel<<<nhist + nprep + ninit, 256>>>(dst, E, convw, x, Wv, N, nhist, nprep);
    scan_kernel<<<1, 1024>>>(N);
    scatter_kernel<<<nhist + nnode, 256>>>(src, dst, (const float4*)eattr, E, N, nhist);

    float* hA = nullptr;
    float* hB = nullptr;
    cudaGetSymbolAddress((void**)&hA, g_h);
    cudaGetSymbolAddress((void**)&hB, g_h2);

    float* hp = hA;
    float* hn = hB;
    int nblk = (N + 127) / 128;
    for (int l = 0; l < NLAYERS; l++) {
        layer_fused_kernel<<<nblk, 512>>>(l, We, convb + (long)l * D, hp, hn, N);  // ours[3] on l==0 -> profiled
        float* t = hp; hp = hn; hn = t;
    }

    pool_kernel<<<G, 128>>>(batch, hp, N);
    mlp_kernel<<<G, 512>>>(Wh1, bh1, Wh2, bh2, out);
    zero_cursor_kernel<<<(N + 255) / 256, 256>>>(N);
}

// round 16
// speedup vs baseline: 1.4329x; 1.4329x over previous
#include <cuda_runtime.h>
#include <cuda_bf16.h>
#include <math.h>
#include <stdint.h>

#define MAXN 50000
#define MAXE 800000
#define D 128
#define NLAYERS 9
#define NGRAPHS 256
#define ONE_PLUS_EPS 1.00001f
#define NPREP_T (NLAYERS * 8 * 16 * 32)   // 36864 prepack threads
#define DBINS 128

// ---------------- scratch (static device globals; zero-initialized at load) ----------------
__device__ float    g_h[MAXN * D];
__device__ float    g_h2[MAXN * D];
__device__ uint32_t g_Ahi[MAXN * 64];     // A split: bf16x2 hi pairs {dim 2j, 2j+1}
__device__ uint32_t g_Alo[MAXN * 64];     // A split: bf16x2 lo pairs
__device__ int      g_rowoff[MAXN + 1];
__device__ int      g_cursor[MAXN];       // STATICALLY ZERO; restored to zero at end of launch
__device__ int      g_srcoff[MAXE];       // src node BYTE offset (src*512) per CSR slot
__device__ float4   g_ea4[MAXE];
__device__ float    g_pooled[NGRAPHS * D];
__device__ int      g_perm[MAXN];         // nodes sorted by degree
__device__ int      g_dcur[DBINS];        // degree-bin cursors (recomputed every launch)
// W prepacked into mma b-fragment layout: [layer][kc(8)][nt(16)][lane(32)] = {bh0,bh1,bl0,bl1}
__device__ uint4    g_Wpk[NPREP_T];

// ---------------- helpers ----------------
__device__ __forceinline__ unsigned short f2bf(float x) {
    __nv_bfloat16 b = __float2bfloat16_rn(x);
    return *(unsigned short*)&b;
}
__device__ __forceinline__ float bf2f(unsigned short u) {
    __nv_bfloat16 b = *(__nv_bfloat16*)&u;
    return __bfloat162float(b);
}
__device__ __forceinline__ uint32_t pack_hi(float a, float b) {
    return (uint32_t)f2bf(a) | ((uint32_t)f2bf(b) << 16);
}
__device__ __forceinline__ uint32_t pack_lo(float a, float b) {
    unsigned short ha = f2bf(a), hb = f2bf(b);
    return (uint32_t)f2bf(a - bf2f(ha)) | ((uint32_t)f2bf(b - bf2f(hb)) << 16);
}
__device__ __forceinline__ void mma_bf16(float* c, uint32_t a0, uint32_t a1, uint32_t a2, uint32_t a3,
                                         uint32_t b0, uint32_t b1) {
    asm volatile(
        "mma.sync.aligned.m16n8k16.row.col.f32.bf16.bf16.f32 "
        "{%0,%1,%2,%3}, {%4,%5,%6,%7}, {%8,%9}, {%0,%1,%2,%3};"
        : "+f"(c[0]), "+f"(c[1]), "+f"(c[2]), "+f"(c[3])
        : "r"(a0), "r"(a1), "r"(a2), "r"(a3), "r"(b0), "r"(b1));
}

// ---------------- fused prologue: hist + W prepack + h init ----------------
__global__ __launch_bounds__(256) void fused_prep_kernel(const int* __restrict__ dst, int E,
                                                         const float* __restrict__ convw,
                                                         const float* __restrict__ x,
                                                         const float* __restrict__ Wv,
                                                         int N, int nhist, int nprep) {
    int b = blockIdx.x;
    int tid = threadIdx.x;
    if (b < nhist) {
        int e = b * 256 + tid;
        if (e < E) atomicAdd(&g_cursor[dst[e]], 1);
    } else if (b < nhist + nprep) {
        int idx = (b - nhist) * 256 + tid;
        if (idx < NPREP_T) {
            int lane = idx & 31;
            int nt = (idx >> 5) & 15;
            int kc = (idx >> 9) & 7;
            int l = idx >> 12;
            const float* W = convw + (long)l * D * D;
            int k0 = kc * 16 + (lane & 3) * 2;
            int n = nt * 8 + (lane >> 2);
            float w00 = W[(k0 + 0) * D + n];
            float w01 = W[(k0 + 1) * D + n];
            float w08 = W[(k0 + 8) * D + n];
            float w09 = W[(k0 + 9) * D + n];
            uint4 o;
            o.x = pack_hi(w00, w01);
            o.y = pack_hi(w08, w09);
            o.z = pack_lo(w00, w01);
            o.w = pack_lo(w08, w09);
            g_Wpk[idx] = o;
        }
    } else {
        __shared__ float xr[2][13];
        int sub = tid >> 7;
        int t = tid & 127;
        int node = (b - nhist - nprep) * 2 + sub;
        if (node < N) {
            if (t < 13) xr[sub][t] = x[(long)node * 13 + t];
        }
        __syncthreads();
        if (node < N) {
            float s = 0.f;
#pragma unroll
            for (int k = 0; k < 13; k++) s = fmaf(xr[sub][k], Wv[k * D + t], s);
            g_h[(long)node * D + t] = s;
        }
    }
}

// ---------------- single-block scan: degrees -> offsets; degree-bin offsets ----------------
__global__ void scan_kernel(int N) {
    __shared__ int sums[1024];
    __shared__ int dhist[DBINS];
    int t = threadIdx.x;
    if (t < DBINS) dhist[t] = 0;
    __syncthreads();
    int chunk = (N + 1023) >> 10;
    int b0 = t * chunk;
    int b1 = min(b0 + chunk, N);
    int s = 0;
    for (int i = b0; i < b1; i++) {
        int dv = g_cursor[i];
        s += dv;
        atomicAdd(&dhist[min(dv, DBINS - 1)], 1);
    }
    sums[t] = s;
    __syncthreads();
    for (int off = 1; off < 1024; off <<= 1) {
        int v = (t >= off) ? sums[t - off] : 0;
        __syncthreads();
        sums[t] += v;
        __syncthreads();
    }
    int base = (t == 0) ? 0 : sums[t - 1];
    for (int i = b0; i < b1; i++) {
        int dv = g_cursor[i];
        g_rowoff[i] = base;
        g_cursor[i] = base;
        base += dv;
    }
    if (t == 1023) g_rowoff[N] = sums[1023];
    if (t == 0) {
        int acc = 0;
#pragma unroll 8
        for (int i = 0; i < DBINS; i++) {
            int c = dhist[i];
            g_dcur[i] = acc;
            acc += c;
        }
    }
}

// ---------------- edge scatter + degree-sorted node permutation ----------------
__global__ void scatter_kernel(const int* __restrict__ src, const int* __restrict__ dst,
                               const float4* __restrict__ attr4, int E, int N, int nhist) {
    int b = blockIdx.x;
    int tid = threadIdx.x;
    if (b < nhist) {
        int e = b * 256 + tid;
        if (e >= E) return;
        int d = dst[e];
        int p = atomicAdd(&g_cursor[d], 1);
        g_srcoff[p] = src[e] << 9;
        g_ea4[p] = attr4[e];
    } else {
        int i = (b - nhist) * 256 + tid;
        if (i >= N) return;
        int deg = g_rowoff[i + 1] - g_rowoff[i];
        int pos = atomicAdd(&g_dcur[min(deg, DBINS - 1)], 1);
        g_perm[pos] = i;
    }
}

// ---------------- aggregation: A[n] = (1+eps)h[n] + sum_{e:dst=n} relu(h[src]+attr@We) ----------------
// warp-per-node, degree-sorted assignment (best measured config: R10).
__global__ __launch_bounds__(256) void aggr_kernel(const float* __restrict__ We,
                                                   const float* __restrict__ hp, int N) {
    int gw = (blockIdx.x * blockDim.x + threadIdx.x) >> 5;
    int lane = threadIdx.x & 31;
    if (gw >= N) return;
    int node = g_perm[gw];

    float wk[4][4];
#pragma unroll
    for (int k = 0; k < 4; k++) {
        float4 t = *(const float4*)&We[k * D + lane * 4];
        wk[k][0] = t.x; wk[k][1] = t.y; wk[k][2] = t.z; wk[k][3] = t.w;
    }

    const char* hpc = (const char*)hp + lane * 16;

    float4 acc;
    {
        float4 hv = *(const float4*)(hpc + ((long)node << 9));
        acc.x = ONE_PLUS_EPS * hv.x;
        acc.y = ONE_PLUS_EPS * hv.y;
        acc.z = ONE_PLUS_EPS * hv.z;
        acc.w = ONE_PLUS_EPS * hv.w;
    }
    int e0 = g_rowoff[node];
    int e1 = g_rowoff[node + 1];
#pragma unroll 4
    for (int e = e0; e < e1; e++) {
        int o = g_srcoff[e];
        float4 a = g_ea4[e];
        float4 hs = *(const float4*)(hpc + o);
        float m0 = fmaf(a.x, wk[0][0], fmaf(a.y, wk[1][0], fmaf(a.z, wk[2][0], fmaf(a.w, wk[3][0], hs.x))));
        float m1 = fmaf(a.x, wk[0][1], fmaf(a.y, wk[1][1], fmaf(a.z, wk[2][1], fmaf(a.w, wk[3][1], hs.y))));
        float m2 = fmaf(a.x, wk[0][2], fmaf(a.y, wk[1][2], fmaf(a.z, wk[2][2], fmaf(a.w, wk[3][2], hs.z))));
        float m3 = fmaf(a.x, wk[0][3], fmaf(a.y, wk[1][3], fmaf(a.z, wk[2][3], fmaf(a.w, wk[3][3], hs.w))));
        acc.x += fmaxf(m0, 0.f);
        acc.y += fmaxf(m1, 0.f);
        acc.z += fmaxf(m2, 0.f);
        acc.w += fmaxf(m3, 0.f);
    }

    uint2 hi = make_uint2(pack_hi(acc.x, acc.y), pack_hi(acc.z, acc.w));
    uint2 lo = make_uint2(pack_lo(acc.x, acc.y), pack_lo(acc.z, acc.w));
    *(uint2*)&g_Ahi[(long)node * 64 + lane * 2] = hi;
    *(uint2*)&g_Alo[(long)node * 64 + lane * 2] = lo;
}

// ---------------- node GEMM via mma.sync bf16 (3-term split), W staged in smem ----------------
// 512 threads: 16 warps; warp = 16 rows x 64 cols. Layer's 64KB W-fragment table is
// staged once per block into dynamic smem (8x L2-traffic cut, LDG->LDS in hot loop).
__global__ __launch_bounds__(512) void gemm_mma_kernel(int l,
                                                       const float* __restrict__ bias,
                                                       const float* __restrict__ hp,
                                                       float* __restrict__ hn, int N) {
    extern __shared__ uint4 sW[];   // 4096 uint4 = 64KB
    int tid = threadIdx.x;

    // stage W fragments: 8 uint4 per thread, coalesced
    {
        const uint4* gw = &g_Wpk[(long)l * 4096];
#pragma unroll
        for (int i = 0; i < 8; i++) sW[tid + i * 512] = gw[tid + i * 512];
    }
    __syncthreads();

    int wid = tid >> 5;
    int lane = tid & 31;
    int g = lane >> 2;
    int tg = lane & 3;
    int rowgrp = wid & 7;
    int colhalf = wid >> 3;
    int row0 = blockIdx.x * 128 + rowgrp * 16;
    int r1 = row0 + g;
    int r2 = row0 + g + 8;
    bool v1 = r1 < N;
    bool v2 = r2 < N;

    const uint4* wbase = &sW[colhalf * 8 * 32 + lane];

    float acc[8][4];
#pragma unroll
    for (int nt = 0; nt < 8; nt++)
#pragma unroll
        for (int j = 0; j < 4; j++) acc[nt][j] = 0.f;

#pragma unroll
    for (int kc = 0; kc < 8; kc++) {
        long i1 = (long)r1 * 64 + kc * 8 + tg;
        long i2 = (long)r2 * 64 + kc * 8 + tg;
        uint32_t ah0 = v1 ? g_Ahi[i1]     : 0u;
        uint32_t ah2 = v1 ? g_Ahi[i1 + 4] : 0u;
        uint32_t ah1 = v2 ? g_Ahi[i2]     : 0u;
        uint32_t ah3 = v2 ? g_Ahi[i2 + 4] : 0u;
        uint32_t al0 = v1 ? g_Alo[i1]     : 0u;
        uint32_t al2 = v1 ? g_Alo[i1 + 4] : 0u;
        uint32_t al1 = v2 ? g_Alo[i2]     : 0u;
        uint32_t al3 = v2 ? g_Alo[i2 + 4] : 0u;

        const uint4* bp = wbase + kc * 512;
#pragma unroll
        for (int nt = 0; nt < 8; nt++) {
            uint4 b = bp[nt * 32];
            mma_bf16(acc[nt], ah0, ah1, ah2, ah3, b.x, b.y);  // Ah @ Bh
            mma_bf16(acc[nt], ah0, ah1, ah2, ah3, b.z, b.w);  // Ah @ Bl
            mma_bf16(acc[nt], al0, al1, al2, al3, b.x, b.y);  // Al @ Bh
        }
    }

    // epilogue
#pragma unroll
    for (int nt = 0; nt < 8; nt++) {
        int c0 = colhalf * 64 + nt * 8 + tg * 2;
        float2 bb = *(const float2*)&bias[c0];
        if (v1) {
            float2 h = *(const float2*)&hp[(long)r1 * D + c0];
            float2 o;
            o.x = fmaxf(acc[nt][0] + bb.x, 0.f) + h.x;
            o.y = fmaxf(acc[nt][1] + bb.y, 0.f) + h.y;
            *(float2*)&hn[(long)r1 * D + c0] = o;
        }
        if (v2) {
            float2 h = *(const float2*)&hp[(long)r2 * D + c0];
            float2 o;
            o.x = fmaxf(acc[nt][2] + bb.x, 0.f) + h.x;
            o.y = fmaxf(acc[nt][3] + bb.y, 0.f) + h.y;
            *(float2*)&hn[(long)r2 * D + c0] = o;
        }
    }
}

// ---------------- mean pool per graph + cursor restore (extra blocks) ----------------
__global__ void pool_kernel(const int* __restrict__ batch, const float* __restrict__ h,
                            int N, int G) {
    if ((int)blockIdx.x >= G) {
        // cursor-restore section
        int i = (blockIdx.x - G) * 128 + threadIdx.x;
        if (i < N) g_cursor[i] = 0;
        return;
    }
    int g = blockIdx.x;
    int d = threadIdx.x;
    int lo = 0, hi = N;
    while (lo < hi) { int m = (lo + hi) >> 1; if (batch[m] < g) lo = m + 1; else hi = m; }
    int start = lo;
    lo = start; hi = N;
    while (lo < hi) { int m = (lo + hi) >> 1; if (batch[m] < g + 1) lo = m + 1; else hi = m; }
    int end = lo;
    float s = 0.f;
    for (int n = start; n < end; n++) s += h[(long)n * D + d];
    float cnt = (float)(end - start);
    g_pooled[g * D + d] = s / fmaxf(cnt, 1.0f);
}

// ---------------- MLP head ----------------
__global__ __launch_bounds__(512) void mlp_kernel(const float* __restrict__ Wh1,
                                                  const float* __restrict__ bh1,
                                                  const float* __restrict__ Wh2,
                                                  const float* __restrict__ bh2,
                                                  float* __restrict__ out) {
    int g = blockIdx.x;
    int j = threadIdx.x;
    __shared__ float p[D];
    __shared__ float red[512];
    if (j < D) p[j] = g_pooled[g * D + j];
    __syncthreads();
    float s = bh1[j];
#pragma unroll 8
    for (int k = 0; k < D; k++) s = fmaf(p[k], Wh1[k * 512 + j], s);
    float ge = 0.5f * s * (1.0f + erff(s * 0.70710678118654752f));
    red[j] = ge * Wh2[j];
    __syncthreads();
    for (int off = 256; off > 0; off >>= 1) {
        if (j < off) red[j] += red[j + off];
        __syncthreads();
    }
    if (j == 0) out[g] = red[0] + bh2[0];
}

// ---------------- launcher ----------------
extern "C" void kernel_launch(void* const* d_in, const int* in_sizes, int n_in,
                              void* d_out, int out_size) {
    const float* x     = (const float*)d_in[0];
    const int*   ei    = (const int*)d_in[1];
    const float* eattr = (const float*)d_in[2];
    const int*   batch = (const int*)d_in[3];
    const float* Wv    = (const float*)d_in[4];
    const float* We    = (const float*)d_in[5];
    const float* convw = (const float*)d_in[6];
    const float* convb = (const float*)d_in[7];
    const float* Wh1   = (const float*)d_in[8];
    const float* bh1   = (const float*)d_in[9];
    const float* Wh2   = (const float*)d_in[10];
    const float* bh2   = (const float*)d_in[11];
    float* out = (float*)d_out;

    int N = in_sizes[0] / 13;
    int E = in_sizes[2] / 4;
    int G = out_size;

    const int* src = ei;
    const int* dst = ei + E;

    int nhist = (E + 255) / 256;
    int nprep = (NPREP_T + 255) / 256;
    int ninit = (N + 1) / 2;
    int nnode = (N + 255) / 256;

    // allow 64KB dynamic smem for the gemm (idempotent, non-stream call)
    cudaFuncSetAttribute(gemm_mma_kernel, cudaFuncAttributeMaxDynamicSharedMemorySize, 65536);

    fused_prep_kernel<<<nhist + nprep + ninit, 256>>>(dst, E, convw, x, Wv, N, nhist, nprep);
    scan_kernel<<<1, 1024>>>(N);
    scatter_kernel<<<nhist + nnode, 256>>>(src, dst, (const float4*)eattr, E, N, nhist);

    float* hA = nullptr;
    float* hB = nullptr;
    cudaGetSymbolAddress((void**)&hA, g_h);
    cudaGetSymbolAddress((void**)&hB, g_h2);

    float* hp = hA;
    float* hn = hB;
    int nblk = (N + 127) / 128;
    for (int l = 0; l < NLAYERS; l++) {
        aggr_kernel<<<(N * 32 + 255) / 256, 256>>>(We, hp, N);   // ours[3] on l==0 -> profiled
        gemm_mma_kernel<<<nblk, 512, 65536>>>(l, convb + (long)l * D, hp, hn, N);
        float* t = hp; hp = hn; hn = t;
    }

    int nzero = (N + 127) / 128;
    pool_kernel<<<G + nzero, 128>>>(batch, hp, N, G);
    mlp_kernel<<<G, 512>>>(Wh1, bh1, Wh2, bh2, out);
}

// round 17
// speedup vs baseline: 1.4434x; 1.0074x over previous
#include <cuda_runtime.h>
#include <cuda_bf16.h>
#include <math.h>
#include <stdint.h>

#define MAXN 50000
#define MAXE 800000
#define D 128
#define NLAYERS 9
#define NGRAPHS 256
#define ONE_PLUS_EPS 1.00001f
#define NPREP_T (NLAYERS * 8 * 16 * 32)   // 36864 prepack threads
#define DBINS 128

// ---------------- scratch (static device globals; zero-initialized at load) ----------------
__device__ float    g_h[MAXN * D];
__device__ float    g_h2[MAXN * D];
__device__ uint32_t g_Ahi[MAXN * 64];     // A split: bf16x2 hi pairs {dim 2j, 2j+1}
__device__ uint32_t g_Alo[MAXN * 64];     // A split: bf16x2 lo pairs
__device__ int      g_rowoff[MAXN + 1];
__device__ int      g_cursor[MAXN];       // STATICALLY ZERO; restored to zero at end of launch
__device__ int      g_srcoff[MAXE];       // src node BYTE offset (src*512) per CSR slot
__device__ float4   g_ea4[MAXE];
__device__ float    g_pooled[NGRAPHS * D];
__device__ int      g_perm[MAXN];         // nodes sorted by degree
__device__ int      g_dcur[DBINS];        // degree-bin cursors (recomputed every launch)
// W prepacked into mma b-fragment layout: [layer][kc(8)][nt(16)][lane(32)] = {bh0,bh1,bl0,bl1}
__device__ uint4    g_Wpk[NPREP_T];

// ---------------- helpers ----------------
__device__ __forceinline__ unsigned short f2bf(float x) {
    __nv_bfloat16 b = __float2bfloat16_rn(x);
    return *(unsigned short*)&b;
}
__device__ __forceinline__ float bf2f(unsigned short u) {
    __nv_bfloat16 b = *(__nv_bfloat16*)&u;
    return __bfloat162float(b);
}
__device__ __forceinline__ uint32_t pack_hi(float a, float b) {
    return (uint32_t)f2bf(a) | ((uint32_t)f2bf(b) << 16);
}
__device__ __forceinline__ uint32_t pack_lo(float a, float b) {
    unsigned short ha = f2bf(a), hb = f2bf(b);
    return (uint32_t)f2bf(a - bf2f(ha)) | ((uint32_t)f2bf(b - bf2f(hb)) << 16);
}
__device__ __forceinline__ void mma_bf16(float* c, uint32_t a0, uint32_t a1, uint32_t a2, uint32_t a3,
                                         uint32_t b0, uint32_t b1) {
    asm volatile(
        "mma.sync.aligned.m16n8k16.row.col.f32.bf16.bf16.f32 "
        "{%0,%1,%2,%3}, {%4,%5,%6,%7}, {%8,%9}, {%0,%1,%2,%3};"
        : "+f"(c[0]), "+f"(c[1]), "+f"(c[2]), "+f"(c[3])
        : "r"(a0), "r"(a1), "r"(a2), "r"(a3), "r"(b0), "r"(b1));
}

// ---------------- fused prologue: hist + W prepack + h init ----------------
__global__ __launch_bounds__(256) void fused_prep_kernel(const int* __restrict__ dst, int E,
                                                         const float* __restrict__ convw,
                                                         const float* __restrict__ x,
                                                         const float* __restrict__ Wv,
                                                         int N, int nhist, int nprep) {
    int b = blockIdx.x;
    int tid = threadIdx.x;
    if (b < nhist) {
        int e = b * 256 + tid;
        if (e < E) atomicAdd(&g_cursor[dst[e]], 1);
    } else if (b < nhist + nprep) {
        int idx = (b - nhist) * 256 + tid;
        if (idx < NPREP_T) {
            int lane = idx & 31;
            int nt = (idx >> 5) & 15;
            int kc = (idx >> 9) & 7;
            int l = idx >> 12;
            const float* W = convw + (long)l * D * D;
            int k0 = kc * 16 + (lane & 3) * 2;
            int n = nt * 8 + (lane >> 2);
            float w00 = W[(k0 + 0) * D + n];
            float w01 = W[(k0 + 1) * D + n];
            float w08 = W[(k0 + 8) * D + n];
            float w09 = W[(k0 + 9) * D + n];
            uint4 o;
            o.x = pack_hi(w00, w01);
            o.y = pack_hi(w08, w09);
            o.z = pack_lo(w00, w01);
            o.w = pack_lo(w08, w09);
            g_Wpk[idx] = o;
        }
    } else {
        __shared__ float xr[2][13];
        int sub = tid >> 7;
        int t = tid & 127;
        int node = (b - nhist - nprep) * 2 + sub;
        if (node < N) {
            if (t < 13) xr[sub][t] = x[(long)node * 13 + t];
        }
        __syncthreads();
        if (node < N) {
            float s = 0.f;
#pragma unroll
            for (int k = 0; k < 13; k++) s = fmaf(xr[sub][k], Wv[k * D + t], s);
            g_h[(long)node * D + t] = s;
        }
    }
}

// ---------------- single-block scan: degrees -> offsets; degree-bin offsets ----------------
__global__ void scan_kernel(int N) {
    __shared__ int sums[1024];
    __shared__ int dhist[DBINS];
    int t = threadIdx.x;
    if (t < DBINS) dhist[t] = 0;
    __syncthreads();
    int chunk = (N + 1023) >> 10;
    int b0 = t * chunk;
    int b1 = min(b0 + chunk, N);
    int s = 0;
    for (int i = b0; i < b1; i++) {
        int dv = g_cursor[i];
        s += dv;
        atomicAdd(&dhist[min(dv, DBINS - 1)], 1);
    }
    sums[t] = s;
    __syncthreads();
    for (int off = 1; off < 1024; off <<= 1) {
        int v = (t >= off) ? sums[t - off] : 0;
        __syncthreads();
        sums[t] += v;
        __syncthreads();
    }
    int base = (t == 0) ? 0 : sums[t - 1];
    for (int i = b0; i < b1; i++) {
        int dv = g_cursor[i];
        g_rowoff[i] = base;
        g_cursor[i] = base;
        base += dv;
    }
    if (t == 1023) g_rowoff[N] = sums[1023];
    if (t == 0) {
        int acc = 0;
#pragma unroll 8
        for (int i = 0; i < DBINS; i++) {
            int c = dhist[i];
            g_dcur[i] = acc;
            acc += c;
        }
    }
}

// ---------------- edge scatter + degree-sorted node permutation ----------------
__global__ void scatter_kernel(const int* __restrict__ src, const int* __restrict__ dst,
                               const float4* __restrict__ attr4, int E, int N, int nhist) {
    int b = blockIdx.x;
    int tid = threadIdx.x;
    if (b < nhist) {
        int e = b * 256 + tid;
        if (e >= E) return;
        int d = dst[e];
        int p = atomicAdd(&g_cursor[d], 1);
        g_srcoff[p] = src[e] << 9;
        g_ea4[p] = attr4[e];
    } else {
        int i = (b - nhist) * 256 + tid;
        if (i >= N) return;
        int deg = g_rowoff[i + 1] - g_rowoff[i];
        int pos = atomicAdd(&g_dcur[min(deg, DBINS - 1)], 1);
        g_perm[pos] = i;
    }
}

// ---------------- aggregation: A[n] = (1+eps)h[n] + sum_{e:dst=n} relu(h[src]+attr@We) ----------------
// warp-per-node, degree-sorted assignment (best measured config).
__global__ __launch_bounds__(256) void aggr_kernel(const float* __restrict__ We,
                                                   const float* __restrict__ hp, int N) {
    int gw = (blockIdx.x * blockDim.x + threadIdx.x) >> 5;
    int lane = threadIdx.x & 31;
    if (gw >= N) return;
    int node = g_perm[gw];

    float wk[4][4];
#pragma unroll
    for (int k = 0; k < 4; k++) {
        float4 t = *(const float4*)&We[k * D + lane * 4];
        wk[k][0] = t.x; wk[k][1] = t.y; wk[k][2] = t.z; wk[k][3] = t.w;
    }

    const char* hpc = (const char*)hp + lane * 16;

    float4 acc;
    {
        float4 hv = *(const float4*)(hpc + ((long)node << 9));
        acc.x = ONE_PLUS_EPS * hv.x;
        acc.y = ONE_PLUS_EPS * hv.y;
        acc.z = ONE_PLUS_EPS * hv.z;
        acc.w = ONE_PLUS_EPS * hv.w;
    }
    int e0 = g_rowoff[node];
    int e1 = g_rowoff[node + 1];
#pragma unroll 4
    for (int e = e0; e < e1; e++) {
        int o = g_srcoff[e];
        float4 a = g_ea4[e];
        float4 hs = *(const float4*)(hpc + o);
        float m0 = fmaf(a.x, wk[0][0], fmaf(a.y, wk[1][0], fmaf(a.z, wk[2][0], fmaf(a.w, wk[3][0], hs.x))));
        float m1 = fmaf(a.x, wk[0][1], fmaf(a.y, wk[1][1], fmaf(a.z, wk[2][1], fmaf(a.w, wk[3][1], hs.y))));
        float m2 = fmaf(a.x, wk[0][2], fmaf(a.y, wk[1][2], fmaf(a.z, wk[2][2], fmaf(a.w, wk[3][2], hs.z))));
        float m3 = fmaf(a.x, wk[0][3], fmaf(a.y, wk[1][3], fmaf(a.z, wk[2][3], fmaf(a.w, wk[3][3], hs.w))));
        acc.x += fmaxf(m0, 0.f);
        acc.y += fmaxf(m1, 0.f);
        acc.z += fmaxf(m2, 0.f);
        acc.w += fmaxf(m3, 0.f);
    }

    uint2 hi = make_uint2(pack_hi(acc.x, acc.y), pack_hi(acc.z, acc.w));
    uint2 lo = make_uint2(pack_lo(acc.x, acc.y), pack_lo(acc.z, acc.w));
    *(uint2*)&g_Ahi[(long)node * 64 + lane * 2] = hi;
    *(uint2*)&g_Alo[(long)node * 64 + lane * 2] = lo;
}

// ---------------- node GEMM via mma.sync bf16 (3-term split), W staged in smem ----------------
__global__ __launch_bounds__(512) void gemm_mma_kernel(int l,
                                                       const float* __restrict__ bias,
                                                       const float* __restrict__ hp,
                                                       float* __restrict__ hn, int N) {
    extern __shared__ uint4 sW[];   // 4096 uint4 = 64KB
    int tid = threadIdx.x;

    {
        const uint4* gw = &g_Wpk[(long)l * 4096];
#pragma unroll
        for (int i = 0; i < 8; i++) sW[tid + i * 512] = gw[tid + i * 512];
    }
    __syncthreads();

    int wid = tid >> 5;
    int lane = tid & 31;
    int g = lane >> 2;
    int tg = lane & 3;
    int rowgrp = wid & 7;
    int colhalf = wid >> 3;
    int row0 = blockIdx.x * 128 + rowgrp * 16;
    int r1 = row0 + g;
    int r2 = row0 + g + 8;
    bool v1 = r1 < N;
    bool v2 = r2 < N;

    const uint4* wbase = &sW[colhalf * 8 * 32 + lane];

    float acc[8][4];
#pragma unroll
    for (int nt = 0; nt < 8; nt++)
#pragma unroll
        for (int j = 0; j < 4; j++) acc[nt][j] = 0.f;

#pragma unroll
    for (int kc = 0; kc < 8; kc++) {
        long i1 = (long)r1 * 64 + kc * 8 + tg;
        long i2 = (long)r2 * 64 + kc * 8 + tg;
        uint32_t ah0 = v1 ? g_Ahi[i1]     : 0u;
        uint32_t ah2 = v1 ? g_Ahi[i1 + 4] : 0u;
        uint32_t ah1 = v2 ? g_Ahi[i2]     : 0u;
        uint32_t ah3 = v2 ? g_Ahi[i2 + 4] : 0u;
        uint32_t al0 = v1 ? g_Alo[i1]     : 0u;
        uint32_t al2 = v1 ? g_Alo[i1 + 4] : 0u;
        uint32_t al1 = v2 ? g_Alo[i2]     : 0u;
        uint32_t al3 = v2 ? g_Alo[i2 + 4] : 0u;

        const uint4* bp = wbase + kc * 512;
#pragma unroll
        for (int nt = 0; nt < 8; nt++) {
            uint4 b = bp[nt * 32];
            mma_bf16(acc[nt], ah0, ah1, ah2, ah3, b.x, b.y);  // Ah @ Bh
            mma_bf16(acc[nt], ah0, ah1, ah2, ah3, b.z, b.w);  // Ah @ Bl
            mma_bf16(acc[nt], al0, al1, al2, al3, b.x, b.y);  // Al @ Bh
        }
    }

#pragma unroll
    for (int nt = 0; nt < 8; nt++) {
        int c0 = colhalf * 64 + nt * 8 + tg * 2;
        float2 bb = *(const float2*)&bias[c0];
        if (v1) {
            float2 h = *(const float2*)&hp[(long)r1 * D + c0];
            float2 o;
            o.x = fmaxf(acc[nt][0] + bb.x, 0.f) + h.x;
            o.y = fmaxf(acc[nt][1] + bb.y, 0.f) + h.y;
            *(float2*)&hn[(long)r1 * D + c0] = o;
        }
        if (v2) {
            float2 h = *(const float2*)&hp[(long)r2 * D + c0];
            float2 o;
            o.x = fmaxf(acc[nt][2] + bb.x, 0.f) + h.x;
            o.y = fmaxf(acc[nt][3] + bb.y, 0.f) + h.y;
            *(float2*)&hn[(long)r2 * D + c0] = o;
        }
    }
}

// ---------------- fused pool + MLP head (+ cursor restore on extra blocks) ----------------
// Block g: 4 warpgroups each sum a quarter of graph g's node range; combine in smem;
// then the 512-thread MLP head computes out[g] directly.
__global__ __launch_bounds__(512) void pool_mlp_kernel(const int* __restrict__ batch,
                                                       const float* __restrict__ h,
                                                       const float* __restrict__ Wh1,
                                                       const float* __restrict__ bh1,
                                                       const float* __restrict__ Wh2,
                                                       const float* __restrict__ bh2,
                                                       float* __restrict__ out,
                                                       int N, int G) {
    int tid = threadIdx.x;
    if ((int)blockIdx.x >= G) {
        int i = ((int)blockIdx.x - G) * 512 + tid;
        if (i < N) g_cursor[i] = 0;
        return;
    }
    __shared__ float part[4][128];
    __shared__ float p[D];
    __shared__ float red[512];

    int g = blockIdx.x;
    // binary search graph range (batch sorted)
    int lo = 0, hi = N;
    while (lo < hi) { int m = (lo + hi) >> 1; if (batch[m] < g) lo = m + 1; else hi = m; }
    int start = lo;
    lo = start; hi = N;
    while (lo < hi) { int m = (lo + hi) >> 1; if (batch[m] < g + 1) lo = m + 1; else hi = m; }
    int end = lo;

    int wg = tid >> 7;       // 0..3
    int d = tid & 127;
    int cnt = end - start;
    int chunk = (cnt + 3) >> 2;
    int s0 = start + wg * chunk;
    int s1 = min(s0 + chunk, end);
    float s = 0.f;
    for (int n = s0; n < s1; n++) s += h[(long)n * D + d];
    part[wg][d] = s;
    __syncthreads();
    if (tid < D) {
        float tot = part[0][tid] + part[1][tid] + part[2][tid] + part[3][tid];
        p[tid] = tot / fmaxf((float)cnt, 1.0f);
    }
    __syncthreads();

    // MLP head: j = tid in [0,512)
    float s2 = bh1[tid];
#pragma unroll 8
    for (int k = 0; k < D; k++) s2 = fmaf(p[k], Wh1[k * 512 + tid], s2);
    float ge = 0.5f * s2 * (1.0f + erff(s2 * 0.70710678118654752f));
    red[tid] = ge * Wh2[tid];
    __syncthreads();
    for (int off = 256; off > 0; off >>= 1) {
        if (tid < off) red[tid] += red[tid + off];
        __syncthreads();
    }
    if (tid == 0) out[g] = red[0] + bh2[0];
}

// ---------------- launcher ----------------
extern "C" void kernel_launch(void* const* d_in, const int* in_sizes, int n_in,
                              void* d_out, int out_size) {
    const float* x     = (const float*)d_in[0];
    const int*   ei    = (const int*)d_in[1];
    const float* eattr = (const float*)d_in[2];
    const int*   batch = (const int*)d_in[3];
    const float* Wv    = (const float*)d_in[4];
    const float* We    = (const float*)d_in[5];
    const float* convw = (const float*)d_in[6];
    const float* convb = (const float*)d_in[7];
    const float* Wh1   = (const float*)d_in[8];
    const float* bh1   = (const float*)d_in[9];
    const float* Wh2   = (const float*)d_in[10];
    const float* bh2   = (const float*)d_in[11];
    float* out = (float*)d_out;

    int N = in_sizes[0] / 13;
    int E = in_sizes[2] / 4;
    int G = out_size;

    const int* src = ei;
    const int* dst = ei + E;

    int nhist = (E + 255) / 256;
    int nprep = (NPREP_T + 255) / 256;
    int ninit = (N + 1) / 2;
    int nnode = (N + 255) / 256;

    cudaFuncSetAttribute(gemm_mma_kernel, cudaFuncAttributeMaxDynamicSharedMemorySize, 65536);

    fused_prep_kernel<<<nhist + nprep + ninit, 256>>>(dst, E, convw, x, Wv, N, nhist, nprep);
    scan_kernel<<<1, 1024>>>(N);
    scatter_kernel<<<nhist + nnode, 256>>>(src, dst, (const float4*)eattr, E, N, nhist);

    float* hA = nullptr;
    float* hB = nullptr;
    cudaGetSymbolAddress((void**)&hA, g_h);
    cudaGetSymbolAddress((void**)&hB, g_h2);

    float* hp = hA;
    float* hn = hB;
    int nblk = (N + 127) / 128;
    for (int l = 0; l < NLAYERS; l++) {
        aggr_kernel<<<(N * 32 + 255) / 256, 256>>>(We, hp, N);   // ours[3] on l==0 -> profiled
        gemm_mma_kernel<<<nblk, 512, 65536>>>(l, convb + (long)l * D, hp, hn, N);
        float* t = hp; hp = hn; hn = t;
    }

    int nzero = (N + 511) / 512;
    pool_mlp_kernel<<<G + nzero, 512>>>(batch, hp, Wh1, bh1, Wh2, bh2, out, N, G);
}